// round 16
// baseline (speedup 1.0000x reference)
#include <cuda_runtime.h>
#include <cuda_fp16.h>
#include <cstdint>

#define BB 16
#define CC 256
#define NN 1600
#define NP 1792            // pad rows of g_xhi stay zero
#define N2 1664            // 13*128: y row padding (pad rows stay zero)
#define LOG2E 1.4426950408889634f

// flash9 smem map (107008 B -> occ 2)
#define F_WS    0          // ws[1664] f32
#define F_ML    6656       // [128][2] f32
#define F_MA    7680
#define F_Y     8704       // y hi 64KB (4 ci-chunks x 16KB, 128 rows x 64ch)
#define F_KST   74240      // 2 stages x 16KB (128 rows x 64ch fp16)
#define F_SMEM  107008

// wy smem map (104448 B -> occ 2)
#define WY_KST  0
#define WY_STG  49152
#define WY_XT   0          // overlaps (phase1 only)
#define WY_A    66560      // 32KB fp16 A operand (4 ci-chunks x 8KB)
#define WY_BETA 99328
#define WY_US   100352
#define WY_W4   101376
#define WY_PS   102400
#define WY_SMEM 104448

__device__ __half g_xhi[(size_t)BB * NP * CC];   // pad rows stay zero
__device__ __half g_yhi[(size_t)BB * N2 * CC];   // y' = (x M^T + beta)*log2e; pad rows zero
__device__ __half g_Mhi[CC * CC];                // Mt[d][c] = (W1^T W2)[c][d], fp16

__device__ float g_w[BB * NN];
__device__ float g_r[BB * NN];
__device__ float g_u[CC];
__device__ float g_beta[CC];
__device__ float g_c0;

// ---------------- helpers ----------------
__device__ __forceinline__ void cp16(uint32_t d, const void* s) {
    asm volatile("cp.async.cg.shared.global [%0], [%1], 16;" :: "r"(d), "l"(s) : "memory");
}
__device__ __forceinline__ void ldsm4(uint32_t* r, uint32_t a) {
    asm volatile("ldmatrix.sync.aligned.m8n8.x4.shared.b16 {%0,%1,%2,%3}, [%4];"
        : "=r"(r[0]), "=r"(r[1]), "=r"(r[2]), "=r"(r[3]) : "r"(a));
}
__device__ __forceinline__ void mmaf16(float* d, const uint32_t* a, uint32_t b0, uint32_t b1) {
    asm volatile("mma.sync.aligned.m16n8k16.row.col.f32.f16.f16.f32 "
        "{%0,%1,%2,%3}, {%4,%5,%6,%7}, {%8,%9}, {%0,%1,%2,%3};"
        : "+f"(d[0]), "+f"(d[1]), "+f"(d[2]), "+f"(d[3])
        : "r"(a[0]), "r"(a[1]), "r"(a[2]), "r"(a[3]), "r"(b0), "r"(b1));
}
__device__ __forceinline__ float ex2f(float x) {
    float y;
    asm("ex2.approx.f32 %0, %1;" : "=f"(y) : "f"(x));
    return y;
}
#define CP_COMMIT() asm volatile("cp.async.commit_group;" ::: "memory")
#define CP_WAIT(n)  asm volatile("cp.async.wait_group %0;" :: "n"(n) : "memory")

// ---------------- prep (grid 81): M tiles (0-63), u (64-71), beta (72-79), c0 (80)
__global__ void __launch_bounds__(256) prep(const float* __restrict__ W1,
                                            const float* __restrict__ W2,
                                            const float* __restrict__ b1,
                                            const float* __restrict__ W3,
                                            const float* __restrict__ b3,
                                            const float* __restrict__ W4) {
    int bid = blockIdx.x, tid = threadIdx.x;
    if (bid < 64) {
        __shared__ float S1[128][32];   // W1[j][c0+cl]
        __shared__ float S2[128][32];   // W2[j][d0+dl]
        int c0 = (bid & 7) * 32, d0 = (bid >> 3) * 32;
        int cl = tid & 31, dl = tid >> 5;
        float acc[4] = {0.f, 0.f, 0.f, 0.f};
        for (int half = 0; half < 2; half++) {
            __syncthreads();
            #pragma unroll
            for (int i = 0; i < 4; i++) {
                int idx = tid + i * 256;
                int r = idx >> 3, c4 = (idx & 7) * 4;
                *(float4*)&S1[r][c4] = *(const float4*)&W1[(half * 128 + r) * CC + c0 + c4];
                *(float4*)&S2[r][c4] = *(const float4*)&W2[(half * 128 + r) * CC + d0 + c4];
            }
            __syncthreads();
            #pragma unroll 8
            for (int j = 0; j < 128; j++) {
                float a = S1[j][cl];
                acc[0] += S2[j][dl] * a;
                acc[1] += S2[j][dl + 8] * a;
                acc[2] += S2[j][dl + 16] * a;
                acc[3] += S2[j][dl + 24] * a;
            }
        }
        #pragma unroll
        for (int k = 0; k < 4; k++) {
            int d = d0 + dl + 8 * k, c = c0 + cl;
            g_Mhi[d * CC + c] = __float2half(acc[k]);
        }
        return;
    }
    if (bid < 80) {
        __shared__ float red[8][32];
        bool is_u = bid < 72;
        int c = ((bid - (is_u ? 64 : 72)) << 5) + (tid & 31);
        int g = tid >> 5;
        const float* vec = is_u ? W4 : b1;
        const float* mat = is_u ? W3 : W2;
        float s = 0.f;
        #pragma unroll 8
        for (int cc = g * 32; cc < g * 32 + 32; cc++)
            s += vec[cc] * mat[cc * CC + c];
        red[g][tid & 31] = s;
        __syncthreads();
        if (tid < 32) {
            float t = 0.f;
            #pragma unroll
            for (int q = 0; q < 8; q++) t += red[q][tid];
            if (is_u) g_u[c] = t; else g_beta[c] = t;
        }
        return;
    }
    __shared__ float red[256];
    red[tid] = W4[tid] * b3[tid];
    __syncthreads();
    #pragma unroll
    for (int off = 128; off >= 1; off >>= 1) {
        if (tid < off) red[tid] += red[tid + off];
        __syncthreads();
    }
    if (tid == 0) g_c0 = red[0];
}

// ---------------- wy: transpose+w/r + y GEMM fused (M single fp16 pass) -------
__global__ void __launch_bounds__(256, 2) wy(const float* __restrict__ x,
                                             const float* __restrict__ W4,
                                             const float* __restrict__ b4) {
    extern __shared__ char sm[];
    uint32_t sb = (uint32_t)__cvta_generic_to_shared(sm);
    int b = blockIdx.y, nt = blockIdx.x;
    int tid = threadIdx.x, w = tid >> 5, L = tid & 31;
    int rw = w & 1, cw = w >> 1;
    float* xt  = (float*)(sm + WY_XT);      // [64][257] (phase 1 only)
    float* bsm = (float*)(sm + WY_BETA);
    float* us  = (float*)(sm + WY_US);
    float* w4s = (float*)(sm + WY_W4);
    float2* ps = (float2*)(sm + WY_PS);
    float* stg = (float*)(sm + WY_STG);     // phase 2

    int m0 = nt * 64;
    bsm[tid] = g_beta[tid];
    us[tid]  = g_u[tid];
    w4s[tid] = W4[CC + tid];

    const float* xb = x + (size_t)b * CC * NN + m0;
    for (int i = tid; i < 64 * CC; i += 256) {
        int m = i & 63, c = i >> 6;
        xt[m * 257 + c] = xb[(size_t)c * NN + m];
    }
    __syncthreads();

    {
        int m = tid >> 2, ci = tid & 3;
        __half hb[64];
        #pragma unroll
        for (int j = 0; j < 64; j++)
            hb[j] = __float2half(xt[m * 257 + ci * 64 + j]);
        size_t gbase = ((size_t)b * NP + m0 + m) * CC + ci * 64;
        uint32_t abase = sb + WY_A + ci * 8192 + m * 128;
        #pragma unroll
        for (int q = 0; q < 8; q++) {
            *(uint4*)&g_xhi[gbase + q * 8] = ((uint4*)hb)[q];
            *(uint4*)(sm + (abase - sb) + ((q ^ (m & 7)) << 4)) = ((uint4*)hb)[q];
        }
    }
    {
        int m = tid >> 2, qq = tid & 3;
        float aw = 0.f, ar = 0.f;
        #pragma unroll 8
        for (int c = qq * 64; c < qq * 64 + 64; c++) {
            float xv = xt[m * 257 + c];
            aw += xv * us[c];
            ar += xv * w4s[c];
        }
        ps[(m << 2) + qq] = make_float2(aw, ar);
    }
    __syncthreads();   // xt dead; region0 becomes KST/stg

    if (tid < 64) {
        float aw = 0.f, ar = 0.f;
        #pragma unroll
        for (int q = 0; q < 4; q++) { float2 p = ps[(tid << 2) + q]; aw += p.x; ar += p.y; }
        g_w[b * NN + m0 + tid] = aw + g_c0;
        g_r[b * NN + m0 + tid] = ar + b4[0];
    }

    // ---- phase 2: y GEMM, single fp16 M pass, 2 output d-chunks, 8 sc ----
    auto fill = [&](int sc) {
        int t = sc >> 2, ci = sc & 3, slot = sc % 3;
        uint32_t base = sb + WY_KST + slot * 16384;
        #pragma unroll
        for (int i = 0; i < 4; i++) {
            int idx = tid + i * 256;
            int r = idx >> 3, kg = idx & 7;
            uint32_t d = base + r * 128 + ((kg ^ (r & 7)) << 4);
            cp16(d, g_Mhi + (size_t)(t * 128 + r) * CC + ci * 64 + kg * 8);
        }
    };
    fill(0); CP_COMMIT();
    fill(1); CP_COMMIT();

    int ar0 = rw * 32 + (L & 15);
    int br0 = cw * 32 + ((L >> 3) & 1) * 8 + (L & 7);
    int colg = L >> 4;
    uint32_t offA[4], offB[4];
    #pragma unroll
    for (int ks = 0; ks < 4; ks++) {
        offA[ks] = (uint32_t)(((ks * 2 + colg) ^ (ar0 & 7)) << 4);
        offB[ks] = (uint32_t)(((ks * 2 + colg) ^ (br0 & 7)) << 4);
    }
    uint32_t aBase = sb + WY_A + ar0 * 128;
    float S[2][4][4];

    for (int sc = 0; sc < 8; sc++) {
        int ci = sc & 3;
        CP_WAIT(1);
        __syncthreads();
        if (sc + 2 < 8) fill(sc + 2);
        CP_COMMIT();
        if (ci == 0) {
            #pragma unroll
            for (int rt = 0; rt < 2; rt++)
                #pragma unroll
                for (int n = 0; n < 4; n++)
                    #pragma unroll
                    for (int e = 0; e < 4; e++) S[rt][n][e] = 0.f;
        }
        uint32_t qb = aBase + ci * 8192;
        uint32_t kb = sb + WY_KST + (sc % 3) * 16384 + br0 * 128;
        #pragma unroll
        for (int ks = 0; ks < 4; ks++) {
            uint32_t ah0[4], ah1[4], bh0[4], bh1[4];
            ldsm4(ah0, qb + offA[ks]);
            ldsm4(ah1, qb + 2048 + offA[ks]);
            ldsm4(bh0, kb + offB[ks]);
            ldsm4(bh1, kb + 2048 + offB[ks]);
            mmaf16(S[0][0], ah0, bh0[0], bh0[2]); mmaf16(S[0][1], ah0, bh0[1], bh0[3]);
            mmaf16(S[0][2], ah0, bh1[0], bh1[2]); mmaf16(S[0][3], ah0, bh1[1], bh1[3]);
            mmaf16(S[1][0], ah1, bh0[0], bh0[2]); mmaf16(S[1][1], ah1, bh0[1], bh0[3]);
            mmaf16(S[1][2], ah1, bh1[0], bh1[2]); mmaf16(S[1][3], ah1, bh1[1], bh1[3]);
        }
        if (ci == 3) {
            int t = sc >> 2;
            #pragma unroll
            for (int h = 0; h < 2; h++) {
                __syncthreads();
                if ((cw >> 1) == h) {
                    int cbase = (cw & 1) * 32;
                    #pragma unroll
                    for (int rt = 0; rt < 2; rt++)
                        #pragma unroll
                        for (int n = 0; n < 4; n++) {
                            int row = rw * 32 + rt * 16 + (L >> 2);
                            int col = cbase + n * 8 + (L & 3) * 2;
                            *(float2*)&stg[row * 68 + col] = make_float2(S[rt][n][0], S[rt][n][1]);
                            *(float2*)&stg[(row + 8) * 68 + col] = make_float2(S[rt][n][2], S[rt][n][3]);
                        }
                }
                __syncthreads();
                {
                    int r = tid >> 2, cs = tid & 3;
                    __half hb[16];
                    #pragma unroll
                    for (int j = 0; j < 16; j++) {
                        float v = (stg[r * 68 + cs * 16 + j] +
                                   bsm[t * 128 + h * 64 + cs * 16 + j]) * LOG2E;
                        hb[j] = __float2half(v);
                    }
                    size_t base = ((size_t)b * N2 + m0 + r) * CC + t * 128 + h * 64 + cs * 16;
                    *(uint4*)&g_yhi[base] = ((uint4*)hb)[0];
                    *(uint4*)&g_yhi[base + 8] = ((uint4*)hb)[1];
                }
            }
        }
    }
}

// ---------------- flash9: 128-row CTAs, 32x64 warp tiles, occ 2 ---------------
// grid (13, 16). 4 row-warps x 2 col-warps. y pad rows (>=1600) are zero.
__global__ void __launch_bounds__(256, 2) flash9(float* __restrict__ outp) {
    extern __shared__ char sm[];
    uint32_t sb = (uint32_t)__cvta_generic_to_shared(sm);
    int b = blockIdx.y, nt = blockIdx.x;
    int tid = threadIdx.x, w = tid >> 5, L = tid & 31;
    int rw = w & 3, cw = w >> 2;          // 4 row-warps (32 rows), 2 col-warps (64 cols)
    float* ws = (float*)(sm + F_WS);

    for (int i = tid; i < N2; i += 256) ws[i] = (i < NN) ? g_w[b * NN + i] : 0.f;

    {
        // y tile: 128 rows x 256 ch -> 4 ci-chunks of [128][64ch], swizzled
        const __half* yh = g_yhi + ((size_t)b * N2 + nt * 128) * CC;
        for (int s = tid; s < 4096; s += 256) {
            int r = s >> 5, c16 = s & 31;
            uint32_t d = sb + F_Y + (c16 >> 3) * 16384 + r * 128 + (((c16 & 7) ^ (r & 7)) << 4);
            cp16(d, yh + r * CC + c16 * 8);
        }
    }
    auto fill = [&](int sc) {
        int t = sc >> 2, ci = sc & 3, slot = sc & 1;
        uint32_t base = sb + F_KST + slot * 16384;
        #pragma unroll
        for (int i = 0; i < 4; i++) {
            int idx = tid + i * 256;
            int r = idx >> 3, kg = idx & 7;      // r 0..127
            uint32_t d = base + r * 128 + ((kg ^ (r & 7)) << 4);
            cp16(d, g_xhi + ((size_t)b * NP + t * 128 + r) * CC + ci * 64 + kg * 8);
        }
    };
    fill(0); CP_COMMIT();

    int ar0 = rw * 32 + (L & 15);
    int br0 = cw * 64 + ((L >> 3) & 1) * 8 + (L & 7);
    int colg = L >> 4;
    uint32_t offA[4], offB[4];
    #pragma unroll
    for (int ks = 0; ks < 4; ks++) {
        offA[ks] = (uint32_t)(((ks * 2 + colg) ^ (ar0 & 7)) << 4);
        offB[ks] = (uint32_t)(((ks * 2 + colg) ^ (br0 & 7)) << 4);
    }
    uint32_t aBase = sb + F_Y + ar0 * 128;
    float S[2][8][4];
    float Lr[4], Ar[4];
    #pragma unroll
    for (int rr = 0; rr < 4; rr++) { Lr[rr] = 0.f; Ar[rr] = 0.f; }

    for (int sc = 0; sc < 52; sc++) {
        int t = sc >> 2, ci = sc & 3;
        CP_WAIT(0);
        __syncthreads();
        if (sc + 1 < 52) fill(sc + 1);
        CP_COMMIT();
        if (ci == 0) {
            #pragma unroll
            for (int rt = 0; rt < 2; rt++)
                #pragma unroll
                for (int n = 0; n < 8; n++)
                    #pragma unroll
                    for (int e = 0; e < 4; e++) S[rt][n][e] = 0.f;
        }
        uint32_t qb = aBase + ci * 16384;
        uint32_t kb = sb + F_KST + (sc & 1) * 16384 + br0 * 128;
        #pragma unroll
        for (int ks = 0; ks < 4; ks++) {
            uint32_t ah0[4], ah1[4], bf[4][4];
            ldsm4(ah0, qb + offA[ks]);
            ldsm4(ah1, qb + 2048 + offA[ks]);
            #pragma unroll
            for (int g = 0; g < 4; g++)
                ldsm4(bf[g], kb + g * 2048 + offB[ks]);
            #pragma unroll
            for (int g = 0; g < 4; g++) {
                mmaf16(S[0][2*g],   ah0, bf[g][0], bf[g][2]);
                mmaf16(S[0][2*g+1], ah0, bf[g][1], bf[g][3]);
                mmaf16(S[1][2*g],   ah1, bf[g][0], bf[g][2]);
                mmaf16(S[1][2*g+1], ah1, bf[g][1], bf[g][3]);
            }
        }
        // no-max softmax; y pre-scaled by log2e -> bare EX2.
        // tail: t==12 cols 1536..1663; cw==1 covers 1600..1663 (all pad) -> skip
        if (ci == 3 && !(t == 12 && cw == 1)) {
            float2 wv[8];
            #pragma unroll
            for (int n = 0; n < 8; n++)
                wv[n] = *(const float2*)(ws + t * 128 + cw * 64 + n * 8 + (L & 3) * 2);
            #pragma unroll
            for (int rr = 0; rr < 4; rr++) {
                int rt = rr >> 1, e0 = (rr & 1) << 1;
                float sl = 0.f, sa = 0.f;
                #pragma unroll
                for (int n = 0; n < 8; n++) {
                    float ea = ex2f(S[rt][n][e0]);
                    float eb = ex2f(S[rt][n][e0 + 1]);
                    sl += ea + eb;
                    sa += ea * wv[n].x + eb * wv[n].y;
                }
                Lr[rr] += sl;
                Ar[rr] += sa;
            }
        }
    }

    // quad-level additive merge, then [128][2] partials
    #pragma unroll
    for (int off = 1; off <= 2; off <<= 1) {
        #pragma unroll
        for (int rr = 0; rr < 4; rr++) {
            Lr[rr] += __shfl_xor_sync(0xffffffffu, Lr[rr], off);
            Ar[rr] += __shfl_xor_sync(0xffffffffu, Ar[rr], off);
        }
    }
    __syncthreads();
    float* ml = (float*)(sm + F_ML);
    float* ma = (float*)(sm + F_MA);
    if ((L & 3) == 0) {
        #pragma unroll
        for (int rr = 0; rr < 4; rr++) {
            int row = rw * 32 + (rr >> 1) * 16 + (L >> 2) + ((rr & 1) << 3);
            ml[row * 2 + cw] = Lr[rr];
            ma[row * 2 + cw] = Ar[rr];
        }
    }
    __syncthreads();
    if (tid < 128) {
        float Ls = ml[tid * 2] + ml[tid * 2 + 1];
        float As = ma[tid * 2] + ma[tid * 2 + 1];
        int n = nt * 128 + tid;
        if (n < NN)
            outp[b * NN + n] = As / Ls + g_r[b * NN + n];
    }
}

// ---------------------------------------------------------------------------
extern "C" void kernel_launch(void* const* d_in, const int* in_sizes, int n_in,
                              void* d_out, int out_size) {
    const float* x  = (const float*)d_in[0];
    const float* W1 = (const float*)d_in[1];
    const float* b1 = (const float*)d_in[2];
    const float* W2 = (const float*)d_in[3];
    const float* b2 = (const float*)d_in[4];
    const float* W3 = (const float*)d_in[5];
    const float* b3 = (const float*)d_in[6];
    const float* W4 = (const float*)d_in[7];
    const float* b4 = (const float*)d_in[8];
    float* out = (float*)d_out;
    (void)b2;  // b2 adds only row-constants, cancelled by softmax

    cudaFuncSetAttribute(wy,     cudaFuncAttributeMaxDynamicSharedMemorySize, WY_SMEM);
    cudaFuncSetAttribute(flash9, cudaFuncAttributeMaxDynamicSharedMemorySize, F_SMEM);

    prep<<<81, 256>>>(W1, W2, b1, W3, b3, W4);
    wy<<<dim3(25, BB), 256, WY_SMEM>>>(x, W4, b4);
    flash9<<<dim3(13, BB), 256, F_SMEM>>>(out);
}

// round 17
// speedup vs baseline: 1.1770x; 1.1770x over previous
#include <cuda_runtime.h>
#include <cuda_fp16.h>
#include <cstdint>

#define BB 16
#define CC 256
#define NN 1600
#define NP 1792            // pad rows of g_xhi stay zero
#define LOG2E 1.4426950408889634f

// flash10 smem map (107008 B -> occ 2)
#define F_WS    0          // ws[1664] f32
#define F_ML    6656       // [64][4]
#define F_MA    7680
#define F_Y     8704       // y hi 32KB (4 ci-chunks x 8KB)
#define F_KST   41472      // 4 stages x 16KB (128 rows x 64ch fp16)
#define F_SMEM  107008

// wy smem map (104448 B -> occ 2)
#define WY_KST  0
#define WY_STG  49152
#define WY_XT   0          // overlaps (phase1 only)
#define WY_A    66560      // 32KB fp16 A operand (4 ci-chunks x 8KB)
#define WY_BETA 99328
#define WY_US   100352
#define WY_W4   101376
#define WY_PS   102400
#define WY_SMEM 104448

__device__ __half g_xhi[(size_t)BB * NP * CC];   // pad rows stay zero
__device__ __half g_yhi[(size_t)BB * NN * CC];   // y' = (x M^T + beta)*log2e, fp16
__device__ __half g_Mhi[CC * CC];                // Mt[d][c] = (W1^T W2)[c][d], fp16

__device__ float g_w[BB * NN];
__device__ float g_r[BB * NN];
__device__ float g_u[CC];
__device__ float g_beta[CC];
__device__ float g_c0;

// ---------------- helpers ----------------
__device__ __forceinline__ void cp16(uint32_t d, const void* s) {
    asm volatile("cp.async.cg.shared.global [%0], [%1], 16;" :: "r"(d), "l"(s) : "memory");
}
__device__ __forceinline__ void ldsm4(uint32_t* r, uint32_t a) {
    asm volatile("ldmatrix.sync.aligned.m8n8.x4.shared.b16 {%0,%1,%2,%3}, [%4];"
        : "=r"(r[0]), "=r"(r[1]), "=r"(r[2]), "=r"(r[3]) : "r"(a));
}
__device__ __forceinline__ void mmaf16(float* d, const uint32_t* a, uint32_t b0, uint32_t b1) {
    asm volatile("mma.sync.aligned.m16n8k16.row.col.f32.f16.f16.f32 "
        "{%0,%1,%2,%3}, {%4,%5,%6,%7}, {%8,%9}, {%0,%1,%2,%3};"
        : "+f"(d[0]), "+f"(d[1]), "+f"(d[2]), "+f"(d[3])
        : "r"(a[0]), "r"(a[1]), "r"(a[2]), "r"(a[3]), "r"(b0), "r"(b1));
}
__device__ __forceinline__ float ex2f(float x) {
    float y;
    asm("ex2.approx.f32 %0, %1;" : "=f"(y) : "f"(x));
    return y;
}
#define CP_COMMIT() asm volatile("cp.async.commit_group;" ::: "memory")
#define CP_WAIT(n)  asm volatile("cp.async.wait_group %0;" :: "n"(n) : "memory")

// ---------------- prep (grid 81): M tiles (0-63), u (64-71), beta (72-79), c0 (80)
__global__ void __launch_bounds__(256) prep(const float* __restrict__ W1,
                                            const float* __restrict__ W2,
                                            const float* __restrict__ b1,
                                            const float* __restrict__ W3,
                                            const float* __restrict__ b3,
                                            const float* __restrict__ W4) {
    int bid = blockIdx.x, tid = threadIdx.x;
    if (bid < 64) {
        __shared__ float S1[128][32];   // W1[j][c0+cl]
        __shared__ float S2[128][32];   // W2[j][d0+dl]
        int c0 = (bid & 7) * 32, d0 = (bid >> 3) * 32;
        int cl = tid & 31, dl = tid >> 5;
        float acc[4] = {0.f, 0.f, 0.f, 0.f};
        for (int half = 0; half < 2; half++) {
            __syncthreads();
            #pragma unroll
            for (int i = 0; i < 4; i++) {
                int idx = tid + i * 256;
                int r = idx >> 3, c4 = (idx & 7) * 4;
                *(float4*)&S1[r][c4] = *(const float4*)&W1[(half * 128 + r) * CC + c0 + c4];
                *(float4*)&S2[r][c4] = *(const float4*)&W2[(half * 128 + r) * CC + d0 + c4];
            }
            __syncthreads();
            #pragma unroll 8
            for (int j = 0; j < 128; j++) {
                float a = S1[j][cl];
                acc[0] += S2[j][dl] * a;
                acc[1] += S2[j][dl + 8] * a;
                acc[2] += S2[j][dl + 16] * a;
                acc[3] += S2[j][dl + 24] * a;
            }
        }
        #pragma unroll
        for (int k = 0; k < 4; k++) {
            int d = d0 + dl + 8 * k, c = c0 + cl;
            g_Mhi[d * CC + c] = __float2half(acc[k]);
        }
        return;
    }
    if (bid < 80) {
        __shared__ float red[8][32];
        bool is_u = bid < 72;
        int c = ((bid - (is_u ? 64 : 72)) << 5) + (tid & 31);
        int g = tid >> 5;
        const float* vec = is_u ? W4 : b1;
        const float* mat = is_u ? W3 : W2;
        float s = 0.f;
        #pragma unroll 8
        for (int cc = g * 32; cc < g * 32 + 32; cc++)
            s += vec[cc] * mat[cc * CC + c];
        red[g][tid & 31] = s;
        __syncthreads();
        if (tid < 32) {
            float t = 0.f;
            #pragma unroll
            for (int q = 0; q < 8; q++) t += red[q][tid];
            if (is_u) g_u[c] = t; else g_beta[c] = t;
        }
        return;
    }
    __shared__ float red[256];
    red[tid] = W4[tid] * b3[tid];
    __syncthreads();
    #pragma unroll
    for (int off = 128; off >= 1; off >>= 1) {
        if (tid < off) red[tid] += red[tid + off];
        __syncthreads();
    }
    if (tid == 0) g_c0 = red[0];
}

// ---------------- wy: transpose+w/r + y GEMM fused (M single fp16 pass) -------
__global__ void __launch_bounds__(256, 2) wy(const float* __restrict__ x,
                                             const float* __restrict__ W4,
                                             const float* __restrict__ b4) {
    extern __shared__ char sm[];
    uint32_t sb = (uint32_t)__cvta_generic_to_shared(sm);
    int b = blockIdx.y, nt = blockIdx.x;
    int tid = threadIdx.x, w = tid >> 5, L = tid & 31;
    int rw = w & 1, cw = w >> 1;
    float* xt  = (float*)(sm + WY_XT);      // [64][257] (phase 1 only)
    float* bsm = (float*)(sm + WY_BETA);
    float* us  = (float*)(sm + WY_US);
    float* w4s = (float*)(sm + WY_W4);
    float2* ps = (float2*)(sm + WY_PS);
    float* stg = (float*)(sm + WY_STG);     // phase 2

    int m0 = nt * 64;
    bsm[tid] = g_beta[tid];
    us[tid]  = g_u[tid];
    w4s[tid] = W4[CC + tid];

    const float* xb = x + (size_t)b * CC * NN + m0;
    for (int i = tid; i < 64 * CC; i += 256) {
        int m = i & 63, c = i >> 6;
        xt[m * 257 + c] = xb[(size_t)c * NN + m];
    }
    __syncthreads();

    {
        int m = tid >> 2, ci = tid & 3;
        __half hb[64];
        #pragma unroll
        for (int j = 0; j < 64; j++)
            hb[j] = __float2half(xt[m * 257 + ci * 64 + j]);
        size_t gbase = ((size_t)b * NP + m0 + m) * CC + ci * 64;
        uint32_t abase = sb + WY_A + ci * 8192 + m * 128;
        #pragma unroll
        for (int q = 0; q < 8; q++) {
            *(uint4*)&g_xhi[gbase + q * 8] = ((uint4*)hb)[q];
            *(uint4*)(sm + (abase - sb) + ((q ^ (m & 7)) << 4)) = ((uint4*)hb)[q];
        }
    }
    {
        int m = tid >> 2, qq = tid & 3;
        float aw = 0.f, ar = 0.f;
        #pragma unroll 8
        for (int c = qq * 64; c < qq * 64 + 64; c++) {
            float xv = xt[m * 257 + c];
            aw += xv * us[c];
            ar += xv * w4s[c];
        }
        ps[(m << 2) + qq] = make_float2(aw, ar);
    }
    __syncthreads();   // xt dead; region0 becomes KST/stg

    if (tid < 64) {
        float aw = 0.f, ar = 0.f;
        #pragma unroll
        for (int q = 0; q < 4; q++) { float2 p = ps[(tid << 2) + q]; aw += p.x; ar += p.y; }
        g_w[b * NN + m0 + tid] = aw + g_c0;
        g_r[b * NN + m0 + tid] = ar + b4[0];
    }

    // ---- phase 2: y GEMM, single fp16 M pass, 2 output d-chunks, 8 sc ----
    auto fill = [&](int sc) {
        int t = sc >> 2, ci = sc & 3, slot = sc % 3;
        uint32_t base = sb + WY_KST + slot * 16384;
        #pragma unroll
        for (int i = 0; i < 4; i++) {
            int idx = tid + i * 256;
            int r = idx >> 3, kg = idx & 7;
            uint32_t d = base + r * 128 + ((kg ^ (r & 7)) << 4);
            cp16(d, g_Mhi + (size_t)(t * 128 + r) * CC + ci * 64 + kg * 8);
        }
    };
    fill(0); CP_COMMIT();
    fill(1); CP_COMMIT();

    int ar0 = rw * 32 + (L & 15);
    int br0 = cw * 32 + ((L >> 3) & 1) * 8 + (L & 7);
    int colg = L >> 4;
    uint32_t offA[4], offB[4];
    #pragma unroll
    for (int ks = 0; ks < 4; ks++) {
        offA[ks] = (uint32_t)(((ks * 2 + colg) ^ (ar0 & 7)) << 4);
        offB[ks] = (uint32_t)(((ks * 2 + colg) ^ (br0 & 7)) << 4);
    }
    uint32_t aBase = sb + WY_A + ar0 * 128;
    float S[2][4][4];

    for (int sc = 0; sc < 8; sc++) {
        int ci = sc & 3;
        CP_WAIT(1);
        __syncthreads();
        if (sc + 2 < 8) fill(sc + 2);
        CP_COMMIT();
        if (ci == 0) {
            #pragma unroll
            for (int rt = 0; rt < 2; rt++)
                #pragma unroll
                for (int n = 0; n < 4; n++)
                    #pragma unroll
                    for (int e = 0; e < 4; e++) S[rt][n][e] = 0.f;
        }
        uint32_t qb = aBase + ci * 8192;
        uint32_t kb = sb + WY_KST + (sc % 3) * 16384 + br0 * 128;
        #pragma unroll
        for (int ks = 0; ks < 4; ks++) {
            uint32_t ah0[4], ah1[4], bh0[4], bh1[4];
            ldsm4(ah0, qb + offA[ks]);
            ldsm4(ah1, qb + 2048 + offA[ks]);
            ldsm4(bh0, kb + offB[ks]);
            ldsm4(bh1, kb + 2048 + offB[ks]);
            mmaf16(S[0][0], ah0, bh0[0], bh0[2]); mmaf16(S[0][1], ah0, bh0[1], bh0[3]);
            mmaf16(S[0][2], ah0, bh1[0], bh1[2]); mmaf16(S[0][3], ah0, bh1[1], bh1[3]);
            mmaf16(S[1][0], ah1, bh0[0], bh0[2]); mmaf16(S[1][1], ah1, bh0[1], bh0[3]);
            mmaf16(S[1][2], ah1, bh1[0], bh1[2]); mmaf16(S[1][3], ah1, bh1[1], bh1[3]);
        }
        if (ci == 3) {
            int t = sc >> 2;
            #pragma unroll
            for (int h = 0; h < 2; h++) {
                __syncthreads();
                if ((cw >> 1) == h) {
                    int cbase = (cw & 1) * 32;
                    #pragma unroll
                    for (int rt = 0; rt < 2; rt++)
                        #pragma unroll
                        for (int n = 0; n < 4; n++) {
                            int row = rw * 32 + rt * 16 + (L >> 2);
                            int col = cbase + n * 8 + (L & 3) * 2;
                            *(float2*)&stg[row * 68 + col] = make_float2(S[rt][n][0], S[rt][n][1]);
                            *(float2*)&stg[(row + 8) * 68 + col] = make_float2(S[rt][n][2], S[rt][n][3]);
                        }
                }
                __syncthreads();
                {
                    int r = tid >> 2, cs = tid & 3;
                    __half hb[16];
                    #pragma unroll
                    for (int j = 0; j < 16; j++) {
                        float v = (stg[r * 68 + cs * 16 + j] +
                                   bsm[t * 128 + h * 64 + cs * 16 + j]) * LOG2E;
                        hb[j] = __float2half(v);
                    }
                    size_t base = ((size_t)b * NN + m0 + r) * CC + t * 128 + h * 64 + cs * 16;
                    *(uint4*)&g_yhi[base] = ((uint4*)hb)[0];
                    *(uint4*)&g_yhi[base + 8] = ((uint4*)hb)[1];
                }
            }
        }
    }
}

// ---------------- flash10: 32x32 warp tiles, nested unrolled loops, 4-stage ---
__global__ void __launch_bounds__(256, 2) flash10(float* __restrict__ outp) {
    extern __shared__ char sm[];
    uint32_t sb = (uint32_t)__cvta_generic_to_shared(sm);
    int b = blockIdx.y, nt = blockIdx.x;
    int tid = threadIdx.x, w = tid >> 5, L = tid & 31;
    int rw = w & 1, cw = w >> 1;          // 2 row-warps x 4 col-warps (32 cols each)
    float* ws = (float*)(sm + F_WS);

    for (int i = tid; i < NN; i += 256) ws[i] = g_w[b * NN + i];

    {
        const __half* yh = g_yhi + ((size_t)b * NN + nt * 64) * CC;
        for (int s = tid; s < 2048; s += 256) {
            int r = s >> 5, c16 = s & 31;
            uint32_t d = sb + F_Y + (c16 >> 3) * 8192 + r * 128 + (((c16 & 7) ^ (r & 7)) << 4);
            cp16(d, yh + r * CC + c16 * 8);
        }
    }
    auto fill = [&](int sc) {
        int t = sc >> 2, ci = sc & 3, slot = sc & 3;
        uint32_t base = sb + F_KST + slot * 16384;
        #pragma unroll
        for (int i = 0; i < 4; i++) {
            int idx = tid + i * 256;
            int r = idx >> 3, kg = idx & 7;      // r 0..127
            uint32_t d = base + r * 128 + ((kg ^ (r & 7)) << 4);
            cp16(d, g_xhi + ((size_t)b * NP + t * 128 + r) * CC + ci * 64 + kg * 8);
        }
    };
    fill(0); CP_COMMIT();
    fill(1); CP_COMMIT();
    fill(2); CP_COMMIT();

    int ar0 = rw * 32 + (L & 15);
    int br0 = cw * 32 + ((L >> 3) & 1) * 8 + (L & 7);
    int colg = L >> 4;
    uint32_t offA[4], offB[4];
    #pragma unroll
    for (int ks = 0; ks < 4; ks++) {
        offA[ks] = (uint32_t)(((ks * 2 + colg) ^ (ar0 & 7)) << 4);
        offB[ks] = (uint32_t)(((ks * 2 + colg) ^ (br0 & 7)) << 4);
    }
    uint32_t aBase = sb + F_Y + ar0 * 128;
    float S[2][4][4];
    float Lr[4], Ar[4];
    #pragma unroll
    for (int rr = 0; rr < 4; rr++) { Lr[rr] = 0.f; Ar[rr] = 0.f; }

    for (int t = 0; t < 13; t++) {
        #pragma unroll
        for (int rt = 0; rt < 2; rt++)
            #pragma unroll
            for (int n = 0; n < 4; n++)
                #pragma unroll
                for (int e = 0; e < 4; e++) S[rt][n][e] = 0.f;
        #pragma unroll
        for (int ci = 0; ci < 4; ci++) {
            int sc = t * 4 + ci;
            CP_WAIT(2);
            __syncthreads();
            if (sc + 3 < 52) fill(sc + 3);
            CP_COMMIT();
            uint32_t qb = aBase + ci * 8192;
            uint32_t kb = sb + F_KST + (sc & 3) * 16384 + br0 * 128;
            #pragma unroll
            for (int ks = 0; ks < 4; ks++) {
                uint32_t ah0[4], ah1[4], bh0[4], bh1[4];
                ldsm4(ah0, qb + offA[ks]);
                ldsm4(ah1, qb + 2048 + offA[ks]);
                ldsm4(bh0, kb + offB[ks]);
                ldsm4(bh1, kb + 2048 + offB[ks]);
                mmaf16(S[0][0], ah0, bh0[0], bh0[2]); mmaf16(S[0][1], ah0, bh0[1], bh0[3]);
                mmaf16(S[0][2], ah0, bh1[0], bh1[2]); mmaf16(S[0][3], ah0, bh1[1], bh1[3]);
                mmaf16(S[1][0], ah1, bh0[0], bh0[2]); mmaf16(S[1][1], ah1, bh0[1], bh0[3]);
                mmaf16(S[1][2], ah1, bh1[0], bh1[2]); mmaf16(S[1][3], ah1, bh1[1], bh1[3]);
            }
        }
        // no-max softmax; y pre-scaled by log2e -> bare EX2.
        // tail: t==12 covers m 1536..1663; cw>=2 cols are pad -> skip
        if (!(t == 12 && cw >= 2)) {
            float2 wv[4];
            #pragma unroll
            for (int n = 0; n < 4; n++)
                wv[n] = *(const float2*)(ws + t * 128 + cw * 32 + n * 8 + (L & 3) * 2);
            #pragma unroll
            for (int rr = 0; rr < 4; rr++) {
                int rt = rr >> 1, e0 = (rr & 1) << 1;
                float sl = 0.f, sa = 0.f;
                #pragma unroll
                for (int n = 0; n < 4; n++) {
                    float ea = ex2f(S[rt][n][e0]);
                    float eb = ex2f(S[rt][n][e0 + 1]);
                    sl += ea + eb;
                    sa += ea * wv[n].x + eb * wv[n].y;
                }
                Lr[rr] += sl;
                Ar[rr] += sa;
            }
        }
    }

    // quad-level additive merge, then [64][4] partials
    #pragma unroll
    for (int off = 1; off <= 2; off <<= 1) {
        #pragma unroll
        for (int rr = 0; rr < 4; rr++) {
            Lr[rr] += __shfl_xor_sync(0xffffffffu, Lr[rr], off);
            Ar[rr] += __shfl_xor_sync(0xffffffffu, Ar[rr], off);
        }
    }
    __syncthreads();
    float* ml = (float*)(sm + F_ML);
    float* ma = (float*)(sm + F_MA);
    if ((L & 3) == 0) {
        #pragma unroll
        for (int rr = 0; rr < 4; rr++) {
            int row = rw * 32 + (rr >> 1) * 16 + (L >> 2) + ((rr & 1) << 3);
            ml[row * 4 + cw] = Lr[rr];
            ma[row * 4 + cw] = Ar[rr];
        }
    }
    __syncthreads();
    if (tid < 64) {
        float Ls = 0.f, As = 0.f;
        #pragma unroll
        for (int p = 0; p < 4; p++) { Ls += ml[tid * 4 + p]; As += ma[tid * 4 + p]; }
        int n = nt * 64 + tid;
        outp[b * NN + n] = As / Ls + g_r[b * NN + n];
    }
}

// ---------------------------------------------------------------------------
extern "C" void kernel_launch(void* const* d_in, const int* in_sizes, int n_in,
                              void* d_out, int out_size) {
    const float* x  = (const float*)d_in[0];
    const float* W1 = (const float*)d_in[1];
    const float* b1 = (const float*)d_in[2];
    const float* W2 = (const float*)d_in[3];
    const float* b2 = (const float*)d_in[4];
    const float* W3 = (const float*)d_in[5];
    const float* b3 = (const float*)d_in[6];
    const float* W4 = (const float*)d_in[7];
    const float* b4 = (const float*)d_in[8];
    float* out = (float*)d_out;
    (void)b2;  // b2 adds only row-constants, cancelled by softmax

    cudaFuncSetAttribute(wy,      cudaFuncAttributeMaxDynamicSharedMemorySize, WY_SMEM);
    cudaFuncSetAttribute(flash10, cudaFuncAttributeMaxDynamicSharedMemorySize, F_SMEM);

    prep<<<81, 256>>>(W1, W2, b1, W3, b3, W4);
    wy<<<dim3(25, BB), 256, WY_SMEM>>>(x, W4, b4);
    flash10<<<dim3(25, BB), 256, F_SMEM>>>(out);
}